// round 5
// baseline (speedup 1.0000x reference)
#include <cuda_runtime.h>
#include <cuda_fp16.h>
#include <cuda_bf16.h>
#include <cstdint>

#define L_TOT 4096
#define HID   2560
#define NH    8
#define NKV   4
#define HD    256
#define SEQ   1024
#define QKV_W 4096   // 2048 q + 1024 k + 1024 v columns

// ---------------- device scratch (no dynamic alloc allowed) ----------------
__device__ __half g_Xh [(size_t)L_TOT * HID];          // hidden fp16 [4096][2560]
__device__ __half g_WB [(size_t)HID * QKV_W];          // [2560][4096] packed Wq|Wk|Wv fp16
__device__ __half g_Woh[(size_t)(NH * HD) * HID];      // [2048][2560] Wo fp16
__device__ float  g_qkv[(size_t)L_TOT * QKV_W];        // fp32 pre-norm q|k|v
__device__ __half g_Q[(size_t)NH  * L_TOT * HD];       // [h][t][d], pre-scaled by 1/16
__device__ __half g_K[(size_t)NKV * L_TOT * HD];
__device__ __half g_V[(size_t)NKV * L_TOT * HD];
__device__ __half g_A[(size_t)L_TOT * NH * HD];        // attention output [t][h*HD+d]

// ---------------- PTX helpers ----------------
__device__ __forceinline__ uint32_t sptr(const void* p) {
    return static_cast<uint32_t>(__cvta_generic_to_shared(p));
}
__device__ __forceinline__ void ldsm_x4(uint32_t* r, const void* p) {
    uint32_t a = sptr(p);
    asm volatile("ldmatrix.sync.aligned.m8n8.x4.shared.b16 {%0,%1,%2,%3}, [%4];"
                 : "=r"(r[0]), "=r"(r[1]), "=r"(r[2]), "=r"(r[3]) : "r"(a));
}
__device__ __forceinline__ void ldsm_x4_t(uint32_t* r, const void* p) {
    uint32_t a = sptr(p);
    asm volatile("ldmatrix.sync.aligned.m8n8.x4.trans.shared.b16 {%0,%1,%2,%3}, [%4];"
                 : "=r"(r[0]), "=r"(r[1]), "=r"(r[2]), "=r"(r[3]) : "r"(a));
}
__device__ __forceinline__ void mma_16816(float* c, const uint32_t* a, const uint32_t* b) {
    asm volatile(
        "mma.sync.aligned.m16n8k16.row.col.f32.f16.f16.f32 "
        "{%0,%1,%2,%3}, {%4,%5,%6,%7}, {%8,%9}, {%0,%1,%2,%3};"
        : "+f"(c[0]), "+f"(c[1]), "+f"(c[2]), "+f"(c[3])
        : "r"(a[0]), "r"(a[1]), "r"(a[2]), "r"(a[3]), "r"(b[0]), "r"(b[1]));
}
__device__ __forceinline__ void cp16(void* s, const void* g) {
    uint32_t a = sptr(s);
    asm volatile("cp.async.cg.shared.global [%0], [%1], 16;" :: "r"(a), "l"(g));
}
__device__ __forceinline__ void cp_commit() { asm volatile("cp.async.commit_group;"); }

__device__ __forceinline__ uint32_t packh2(float a, float b) {
    __half2 h = __floats2half2_rn(a, b);
    return *reinterpret_cast<uint32_t*>(&h);
}
__device__ __forceinline__ float qmax(float v) {
    v = fmaxf(v, __shfl_xor_sync(0xffffffffu, v, 1));
    v = fmaxf(v, __shfl_xor_sync(0xffffffffu, v, 2));
    return v;
}
__device__ __forceinline__ float qsum(float v) {
    v += __shfl_xor_sync(0xffffffffu, v, 1);
    v += __shfl_xor_sync(0xffffffffu, v, 2);
    return v;
}

// ---------------- merged fp32->fp16 convert/pack for X + all weights ----------------
#define R0 5242880
#define R1 2621440
#define R2 1310720
#define R3 1310720
#define R4 2621440
#define RTOT (R0 + R1 + R2 + R3 + R4)

__global__ __launch_bounds__(256) void convert_all(
    const float2* __restrict__ X, const float2* __restrict__ Wq,
    const float2* __restrict__ Wk, const float2* __restrict__ Wv,
    const float2* __restrict__ Wo)
{
    int i = blockIdx.x * blockDim.x + threadIdx.x;
    if (i >= RTOT) return;
    __half2* WB = reinterpret_cast<__half2*>(g_WB);
    if (i < R0) {
        float2 v = X[i];
        reinterpret_cast<__half2*>(g_Xh)[i] = __floats2half2_rn(v.x, v.y);
    } else if (i < R0 + R1) {
        int j = i - R0;
        float2 v = Wq[j];
        int k = j >> 10, n = j & 1023;
        WB[(size_t)k * 2048 + n] = __floats2half2_rn(v.x, v.y);
    } else if (i < R0 + R1 + R2) {
        int j = i - (R0 + R1);
        float2 v = Wk[j];
        int k = j >> 9, n = j & 511;
        WB[(size_t)k * 2048 + 1024 + n] = __floats2half2_rn(v.x, v.y);
    } else if (i < R0 + R1 + R2 + R3) {
        int j = i - (R0 + R1 + R2);
        float2 v = Wv[j];
        int k = j >> 9, n = j & 511;
        WB[(size_t)k * 2048 + 1536 + n] = __floats2half2_rn(v.x, v.y);
    } else {
        int j = i - (R0 + R1 + R2 + R3);
        float2 v = Wo[j];
        reinterpret_cast<__half2*>(g_Woh)[j] = __floats2half2_rn(v.x, v.y);
    }
}

// ---------------- fp16 GEMM: C(f32)[M,N] = A(f16)[M,K] * B(f16)[K,N] ----------------
// 256x128x64 tile, 3-stage cp.async pipeline, 8 warps (4x2), warp tile 64x64
#define BM 256
#define BN 128
#define BK 64
#define NSTG 3
#define AS_STRIDE (BK + 8)          // 72 halves
#define BS_STRIDE (BN + 8)          // 136 halves
#define AS_BYTES (BM * AS_STRIDE * 2)          // 36864
#define BS_BYTES (BK * BS_STRIDE * 2)          // 17408
#define STG_BYTES (AS_BYTES + BS_BYTES)        // 54272
#define GEMM_SMEM (NSTG * STG_BYTES)           // 162816

__global__ __launch_bounds__(256) void gemm_f16f32(
    const __half* __restrict__ A, const __half* __restrict__ B,
    float* __restrict__ C, int M, int N, int K, int ldc)
{
    extern __shared__ __align__(16) char dsm[];

    int tid = threadIdx.x;
    int warp = tid >> 5, lane = tid & 31;
    int wm = warp >> 1, wn = warp & 1;       // 4x2 warp grid, warp tile 64x64
    int bm = blockIdx.y * BM, bn = blockIdx.x * BN;
    int nkt = K / BK;

    float acc[4][8][4];
#pragma unroll
    for (int a = 0; a < 4; a++)
#pragma unroll
        for (int b = 0; b < 8; b++)
#pragma unroll
            for (int c = 0; c < 4; c++) acc[a][b][c] = 0.f;

    auto load_stage = [&](int kt) {
        int s = kt % NSTG;
        __half* __restrict__ As = reinterpret_cast<__half*>(dsm + (size_t)s * STG_BYTES);
        __half* __restrict__ Bs = reinterpret_cast<__half*>(dsm + (size_t)s * STG_BYTES + AS_BYTES);
        const __half* Ag = A + (size_t)bm * K + kt * BK;
        const __half* Bg = B + (size_t)(kt * BK) * N + bn;
#pragma unroll
        for (int i = 0; i < 8; i++) {            // A: 256 rows x 8 chunks of 16B
            int v = i * 256 + tid;
            int r = v >> 3, c = v & 7;
            cp16(As + r * AS_STRIDE + c * 8, Ag + (size_t)r * K + c * 8);
        }
#pragma unroll
        for (int i = 0; i < 4; i++) {            // B: 64 rows x 16 chunks of 16B
            int v = i * 256 + tid;
            int r = v >> 4, c = v & 15;
            cp16(Bs + r * BS_STRIDE + c * 8, Bg + (size_t)r * N + c * 8);
        }
        cp_commit();
    };

    load_stage(0); load_stage(1); load_stage(2);

    for (int kt = 0; kt < nkt; kt++) {
        asm volatile("cp.async.wait_group 2;");
        __syncthreads();

        int s = kt % NSTG;
        const __half* __restrict__ As = reinterpret_cast<const __half*>(dsm + (size_t)s * STG_BYTES);
        const __half* __restrict__ Bs = reinterpret_cast<const __half*>(dsm + (size_t)s * STG_BYTES + AS_BYTES);
#pragma unroll
        for (int kk = 0; kk < 4; kk++) {
            uint32_t af[4][4];
#pragma unroll
            for (int mi = 0; mi < 4; mi++)
                ldsm_x4(af[mi], As + (wm * 64 + mi * 16 + (lane & 15)) * AS_STRIDE
                                   + kk * 16 + (lane >> 4) * 8);
            uint32_t bf[4][4];
#pragma unroll
            for (int nj = 0; nj < 4; nj++)
                ldsm_x4_t(bf[nj], Bs + (kk * 16 + (lane & 15)) * BS_STRIDE
                                     + wn * 64 + nj * 16 + (lane >> 4) * 8);
#pragma unroll
            for (int mi = 0; mi < 4; mi++)
#pragma unroll
                for (int ni = 0; ni < 8; ni++)
                    mma_16816(acc[mi][ni], af[mi], &bf[ni >> 1][(ni & 1) * 2]);
        }
        __syncthreads();

        if (kt + NSTG < nkt) load_stage(kt + NSTG);
        else cp_commit();   // keep group accounting uniform
    }

#pragma unroll
    for (int mi = 0; mi < 4; mi++)
#pragma unroll
        for (int ni = 0; ni < 8; ni++) {
            int r0 = bm + wm * 64 + mi * 16 + (lane >> 2);
            int c0 = bn + wn * 64 + ni * 8 + (lane & 3) * 2;
            float2 v0 = make_float2(acc[mi][ni][0], acc[mi][ni][1]);
            float2 v1 = make_float2(acc[mi][ni][2], acc[mi][ni][3]);
            *reinterpret_cast<float2*>(C + (size_t)r0 * ldc + c0)       = v0;
            *reinterpret_cast<float2*>(C + (size_t)(r0 + 8) * ldc + c0) = v1;
        }
}

// ---------------- RMSNorm + RoPE + V-convert (warp per (token, head-slot)) ----------
// slot 0-7: Q heads; 8-11: K heads; 12-15: V heads (plain convert)
__global__ __launch_bounds__(256) void normrope_kernel(
    const float* __restrict__ qkv, const float* __restrict__ cosb,
    const float* __restrict__ sinb, const float* __restrict__ qw,
    const float* __restrict__ kw)
{
    int gw = blockIdx.x * 8 + (threadIdx.x >> 5);
    int lane = threadIdx.x & 31;
    int t = gw >> 4, hh = gw & 15;
    int j = lane * 4;

    if (hh >= 12) {   // V: plain fp32 -> fp16
        int kvh = hh - 12;
        const float* src = qkv + (size_t)t * QKV_W + 3072 + kvh * HD;
        __half* dst = g_V + ((size_t)kvh * L_TOT + t) * HD;
        float4 x1 = *reinterpret_cast<const float4*>(src + j);
        float4 x2 = *reinterpret_cast<const float4*>(src + 128 + j);
        *reinterpret_cast<__half2*>(dst + j)           = __floats2half2_rn(x1.x, x1.y);
        *reinterpret_cast<__half2*>(dst + j + 2)       = __floats2half2_rn(x1.z, x1.w);
        *reinterpret_cast<__half2*>(dst + 128 + j)     = __floats2half2_rn(x2.x, x2.y);
        *reinterpret_cast<__half2*>(dst + 128 + j + 2) = __floats2half2_rn(x2.z, x2.w);
        return;
    }

    const float* src; const float* w; __half* dst; float sc;
    if (hh < 8) {
        src = qkv + (size_t)t * QKV_W + hh * HD;
        w = qw; dst = g_Q + ((size_t)hh * L_TOT + t) * HD;
        sc = 0.0625f;   // fold SCALING = 256^-0.5
    } else {
        int kvh = hh - 8;
        src = qkv + (size_t)t * QKV_W + 2048 + kvh * HD;
        w = kw; dst = g_K + ((size_t)kvh * L_TOT + t) * HD;
        sc = 1.0f;
    }

    float4 x1 = *reinterpret_cast<const float4*>(src + j);
    float4 x2 = *reinterpret_cast<const float4*>(src + 128 + j);

    float ss = x1.x * x1.x + x1.y * x1.y + x1.z * x1.z + x1.w * x1.w
             + x2.x * x2.x + x2.y * x2.y + x2.z * x2.z + x2.w * x2.w;
#pragma unroll
    for (int o = 16; o; o >>= 1) ss += __shfl_xor_sync(0xffffffffu, ss, o);
    float r = rsqrtf(ss * (1.0f / 256.0f) + 1e-6f);

    float4 w1 = *reinterpret_cast<const float4*>(w + j);
    float4 w2 = *reinterpret_cast<const float4*>(w + 128 + j);
    float4 c1 = *reinterpret_cast<const float4*>(cosb + (size_t)t * HD + j);
    float4 c2 = *reinterpret_cast<const float4*>(cosb + (size_t)t * HD + 128 + j);
    float4 s1 = *reinterpret_cast<const float4*>(sinb + (size_t)t * HD + j);
    float4 s2 = *reinterpret_cast<const float4*>(sinb + (size_t)t * HD + 128 + j);

    float n1[4] = { x1.x * r * (1.f + w1.x), x1.y * r * (1.f + w1.y),
                    x1.z * r * (1.f + w1.z), x1.w * r * (1.f + w1.w) };
    float n2[4] = { x2.x * r * (1.f + w2.x), x2.y * r * (1.f + w2.y),
                    x2.z * r * (1.f + w2.z), x2.w * r * (1.f + w2.w) };
    float cA[4] = { c1.x, c1.y, c1.z, c1.w }, cB[4] = { c2.x, c2.y, c2.z, c2.w };
    float sA[4] = { s1.x, s1.y, s1.z, s1.w }, sB[4] = { s2.x, s2.y, s2.z, s2.w };

    __half2 o1[2], o2[2];
#pragma unroll
    for (int i = 0; i < 4; i++) {
        float lo = (n1[i] * cA[i] - n2[i] * sA[i]) * sc;   // d = j+i
        float hi = (n2[i] * cB[i] + n1[i] * sB[i]) * sc;   // d = j+i+128
        reinterpret_cast<__half*>(o1)[i] = __float2half_rn(lo);
        reinterpret_cast<__half*>(o2)[i] = __float2half_rn(hi);
    }
    *reinterpret_cast<__half2*>(dst + j)           = o1[0];
    *reinterpret_cast<__half2*>(dst + j + 2)       = o1[1];
    *reinterpret_cast<__half2*>(dst + 128 + j)     = o2[0];
    *reinterpret_cast<__half2*>(dst + 128 + j + 2) = o2[1];
}

// ---------------- flash attention: CTA = (qtile128, seq, head), 8 warps -------------
#define ATT_STRIDE 264
#define Q_TILE_H (128 * ATT_STRIDE)            // halves
#define KV_TILE_H (64 * ATT_STRIDE)            // halves
#define SMEM_ATTN ((Q_TILE_H + 4 * KV_TILE_H) * 2)   // 202752 bytes

__global__ __launch_bounds__(256) void attn_kernel() {
    extern __shared__ __half sm[];
    __half* sQ = sm;
    __half* sK[2] = { sm + Q_TILE_H,                 sm + Q_TILE_H + 2 * KV_TILE_H };
    __half* sV[2] = { sm + Q_TILE_H + KV_TILE_H,     sm + Q_TILE_H + 3 * KV_TILE_H };

    int tid = threadIdx.x, warp = tid >> 5, lane = tid & 31;
    int qt = blockIdx.x, seq = blockIdx.y, h = blockIdx.z;
    int kvh = h >> 1;

    const __half* Qg = g_Q + ((size_t)h * L_TOT + seq * SEQ + qt * 128) * HD;
    const __half* Kg = g_K + ((size_t)kvh * L_TOT + seq * SEQ) * HD;
    const __half* Vg = g_V + ((size_t)kvh * L_TOT + seq * SEQ) * HD;

#pragma unroll
    for (int i = 0; i < 16; i++) {   // 128 rows x 32 chunks of 16B, 256 threads
        int v = i * 256 + tid, r = v >> 5, cv = v & 31;
        cp16(&sQ[r * ATT_STRIDE + cv * 8], Qg + (size_t)r * HD + cv * 8);
    }
    cp_commit();

    auto loadKV = [&](int kt, int buf) {
#pragma unroll
        for (int i = 0; i < 8; i++) {   // 64 rows x 32 chunks each for K and V
            int v = i * 256 + tid, r = v >> 5, cv = v & 31;
            cp16(&sK[buf][r * ATT_STRIDE + cv * 8], Kg + (size_t)(kt * 64 + r) * HD + cv * 8);
            cp16(&sV[buf][r * ATT_STRIDE + cv * 8], Vg + (size_t)(kt * 64 + r) * HD + cv * 8);
        }
        cp_commit();
    };
    loadKV(0, 0);

    float o[32][4];
#pragma unroll
    for (int nt = 0; nt < 32; nt++)
#pragma unroll
        for (int c = 0; c < 4; c++) o[nt][c] = 0.f;
    float m0 = -1e30f, m1 = -1e30f, l0 = 0.f, l1 = 0.f;

    int nkt = 2 * qt + 2;   // K tiles 0 .. 2qt+1 (causal within 1024-token seq)
    for (int kt = 0; kt < nkt; kt++) {
        int buf = kt & 1;
        if (kt + 1 < nkt) {
            loadKV(kt + 1, buf ^ 1);
            asm volatile("cp.async.wait_group 1;");
        } else {
            asm volatile("cp.async.wait_group 0;");
        }
        __syncthreads();

        float s[8][4];
#pragma unroll
        for (int nt = 0; nt < 8; nt++)
#pragma unroll
            for (int c = 0; c < 4; c++) s[nt][c] = 0.f;

#pragma unroll
        for (int kc = 0; kc < 16; kc++) {
            uint32_t af[4];
            ldsm_x4(af, &sQ[(warp * 16 + (lane & 15)) * ATT_STRIDE + kc * 16 + (lane >> 4) * 8]);
#pragma unroll
            for (int g = 0; g < 4; g++) {
                uint32_t bf[4];
                ldsm_x4(bf, &sK[buf][(g * 16 + (lane & 15)) * ATT_STRIDE + kc * 16 + (lane >> 4) * 8]);
                uint32_t b0[2] = { bf[0], bf[2] };
                uint32_t b1[2] = { bf[1], bf[3] };
                mma_16816(s[2 * g],     af, b0);
                mma_16816(s[2 * g + 1], af, b1);
            }
        }

        if (kt >= 2 * qt) {   // tiles overlapping the diagonal: elementwise causal mask
            int rg = qt * 128 + warp * 16 + (lane >> 2);
            int cb = kt * 64 + (lane & 3) * 2;
#pragma unroll
            for (int nt = 0; nt < 8; nt++) {
                int c = cb + nt * 8;
                if (c     > rg)     s[nt][0] = -1e30f;
                if (c + 1 > rg)     s[nt][1] = -1e30f;
                if (c     > rg + 8) s[nt][2] = -1e30f;
                if (c + 1 > rg + 8) s[nt][3] = -1e30f;
            }
        }

        float mx0 = -1e30f, mx1 = -1e30f;
#pragma unroll
        for (int nt = 0; nt < 8; nt++) {
            mx0 = fmaxf(mx0, fmaxf(s[nt][0], s[nt][1]));
            mx1 = fmaxf(mx1, fmaxf(s[nt][2], s[nt][3]));
        }
        mx0 = qmax(mx0); mx1 = qmax(mx1);
        float nm0 = fmaxf(m0, mx0), nm1 = fmaxf(m1, mx1);
        float a0 = __expf(m0 - nm0), a1 = __expf(m1 - nm1);
        float sum0 = 0.f, sum1 = 0.f;
#pragma unroll
        for (int nt = 0; nt < 8; nt++) {
            s[nt][0] = __expf(s[nt][0] - nm0);
            s[nt][1] = __expf(s[nt][1] - nm0);
            s[nt][2] = __expf(s[nt][2] - nm1);
            s[nt][3] = __expf(s[nt][3] - nm1);
            sum0 += s[nt][0] + s[nt][1];
            sum1 += s[nt][2] + s[nt][3];
        }
        sum0 = qsum(sum0); sum1 = qsum(sum1);
        l0 = l0 * a0 + sum0; l1 = l1 * a1 + sum1;
        m0 = nm0; m1 = nm1;
#pragma unroll
        for (int nt = 0; nt < 32; nt++) {
            o[nt][0] *= a0; o[nt][1] *= a0;
            o[nt][2] *= a1; o[nt][3] *= a1;
        }

#pragma unroll
        for (int j = 0; j < 4; j++) {
            uint32_t af2[4];
            af2[0] = packh2(s[2 * j][0],     s[2 * j][1]);
            af2[1] = packh2(s[2 * j][2],     s[2 * j][3]);
            af2[2] = packh2(s[2 * j + 1][0], s[2 * j + 1][1]);
            af2[3] = packh2(s[2 * j + 1][2], s[2 * j + 1][3]);
#pragma unroll
            for (int g = 0; g < 16; g++) {
                uint32_t bf[4];
                ldsm_x4_t(bf, &sV[buf][(j * 16 + (lane & 15)) * ATT_STRIDE + g * 16 + (lane >> 4) * 8]);
                mma_16816(o[2 * g],     af2, &bf[0]);
                mma_16816(o[2 * g + 1], af2, &bf[2]);
            }
        }
        __syncthreads();
    }

    float i0 = 1.f / l0, i1 = 1.f / l1;
    int row = seq * SEQ + qt * 128 + warp * 16 + (lane >> 2);
    __half* Ob0 = g_A + (size_t)row * (NH * HD) + h * HD;
    __half* Ob1 = g_A + (size_t)(row + 8) * (NH * HD) + h * HD;
#pragma unroll
    for (int nt = 0; nt < 32; nt++) {
        int c = nt * 8 + (lane & 3) * 2;
        *reinterpret_cast<__half2*>(Ob0 + c) = __floats2half2_rn(o[nt][0] * i0, o[nt][1] * i0);
        *reinterpret_cast<__half2*>(Ob1 + c) = __floats2half2_rn(o[nt][2] * i1, o[nt][3] * i1);
    }
}

// ---------------- launch ----------------
extern "C" void kernel_launch(void* const* d_in, const int* in_sizes, int n_in,
                              void* d_out, int out_size) {
    const float* X    = (const float*)d_in[0];
    const float* cosb = (const float*)d_in[1];
    const float* sinb = (const float*)d_in[2];
    const float* Wq   = (const float*)d_in[3];
    const float* Wk   = (const float*)d_in[4];
    const float* Wv   = (const float*)d_in[5];
    const float* Wo   = (const float*)d_in[6];
    const float* qw   = (const float*)d_in[7];
    const float* kw   = (const float*)d_in[8];
    float* out = (float*)d_out;

    void *pXh, *pWB, *pWo, *pqkv, *pA;
    cudaGetSymbolAddress(&pXh,  g_Xh);
    cudaGetSymbolAddress(&pWB,  g_WB);
    cudaGetSymbolAddress(&pWo,  g_Woh);
    cudaGetSymbolAddress(&pqkv, g_qkv);
    cudaGetSymbolAddress(&pA,   g_A);

    convert_all<<<(RTOT + 255) / 256, 256>>>(
        (const float2*)X, (const float2*)Wq, (const float2*)Wk,
        (const float2*)Wv, (const float2*)Wo);

    cudaFuncSetAttribute(gemm_f16f32, cudaFuncAttributeMaxDynamicSharedMemorySize, GEMM_SMEM);

    // fused QKV projection: X[4096,2560] @ WB[2560,4096] -> g_qkv
    gemm_f16f32<<<dim3(QKV_W / BN, L_TOT / BM), 256, GEMM_SMEM>>>(
        (const __half*)pXh, (const __half*)pWB, (float*)pqkv, L_TOT, QKV_W, HID, QKV_W);

    normrope_kernel<<<L_TOT * 16 / 8, 256>>>((const float*)pqkv, cosb, sinb, qw, kw);

    cudaFuncSetAttribute(attn_kernel, cudaFuncAttributeMaxDynamicSharedMemorySize, SMEM_ATTN);
    attn_kernel<<<dim3(SEQ / 128, L_TOT / SEQ, NH), 256, SMEM_ATTN>>>();

    // output projection: g_A[4096,2048] @ Wo[2048,2560] -> out
    gemm_f16f32<<<dim3(HID / BN, L_TOT / BM), 256, GEMM_SMEM>>>(
        (const __half*)pA, (const __half*)pWo, out, L_TOT, HID, NH * HD, HID);
}